// round 3
// baseline (speedup 1.0000x reference)
#include <cuda_runtime.h>
#include <cuda_bf16.h>

// GATLayer reduces analytically: out = x @ W^T.
// The reference's final einsum 'bnjh,bnhd->bnhd' sums alpha over j while h is
// indexed by the output row n, so out = h * (sum_j alpha) = h * 1 = h.
// adj and a_w are dead inputs. This is a single NT SGEMM:
//   M = B*N = 8192, N = OUT_DIM = 256, K = IN_DIM = 256
//   C[m,n] = sum_k A[m,k] * Bm[n,k]   (A = x, Bm = W, both row-major K-minor)

#define BM 128
#define BN 64
#define BK 16
#define TM 8
#define TN 4

__global__ __launch_bounds__(256, 2)
void gat_gemm_nt(const float* __restrict__ A,
                 const float* __restrict__ Bm,
                 float* __restrict__ C,
                 int M, int N, int K)
{
    __shared__ float As[BK][BM];       // [k][m]
    __shared__ float Bs[BK][BN + 4];   // [k][n], pad to dodge conflicts

    const int t = threadIdx.x;
    const int brow = blockIdx.y;
    const int bcol = blockIdx.x;

    const float* Ab = A + (size_t)brow * BM * K;
    const float* Bb = Bm + (size_t)bcol * BN * K;

    const int tm = (t >> 4) * TM;   // 16 row-groups of 8
    const int tn = (t & 15) * TN;   // 16 col-groups of 4

    float acc[TM][TN];
#pragma unroll
    for (int i = 0; i < TM; i++)
#pragma unroll
        for (int j = 0; j < TN; j++) acc[i][j] = 0.f;

    for (int k0 = 0; k0 < K; k0 += BK) {
        // --- Load A tile: 128 rows x 16 k = 512 float4, 2 per thread ---
#pragma unroll
        for (int i = 0; i < 2; i++) {
            int idx = t + i * 256;          // 0..511
            int r  = idx >> 2;              // row 0..127
            int fc = (idx & 3) * 4;         // k offset 0,4,8,12
            float4 v = *(const float4*)(Ab + (size_t)r * K + k0 + fc);
            As[fc + 0][r] = v.x;
            As[fc + 1][r] = v.y;
            As[fc + 2][r] = v.z;
            As[fc + 3][r] = v.w;
        }
        // --- Load B tile: 64 rows x 16 k = 256 float4, 1 per thread ---
        {
            int r  = t >> 2;                // row 0..63
            int fc = (t & 3) * 4;           // k offset 0,4,8,12
            float4 v = *(const float4*)(Bb + (size_t)r * K + k0 + fc);
            Bs[fc + 0][r] = v.x;
            Bs[fc + 1][r] = v.y;
            Bs[fc + 2][r] = v.z;
            Bs[fc + 3][r] = v.w;
        }
        __syncthreads();

#pragma unroll
        for (int k = 0; k < BK; k++) {
            float a[TM], b[TN];
#pragma unroll
            for (int i = 0; i < TM; i++) a[i] = As[k][tm + i];
#pragma unroll
            for (int j = 0; j < TN; j++) b[j] = Bs[k][tn + j];
#pragma unroll
            for (int i = 0; i < TM; i++)
#pragma unroll
                for (int j = 0; j < TN; j++)
                    acc[i][j] = fmaf(a[i], b[j], acc[i][j]);
        }
        __syncthreads();
    }

    // --- Write C: each thread 8 rows x 4 cols, float4 per row ---
    float* Cb = C + (size_t)(brow * BM) * N + bcol * BN;
#pragma unroll
    for (int i = 0; i < TM; i++) {
        float4 v;
        v.x = acc[i][0]; v.y = acc[i][1]; v.z = acc[i][2]; v.w = acc[i][3];
        *(float4*)(Cb + (size_t)(tm + i) * N + tn) = v;
    }
}

extern "C" void kernel_launch(void* const* d_in, const int* in_sizes, int n_in,
                              void* d_out, int out_size)
{
    // metadata order: x (B,N,IN), adj (B,N,N) [unused], W (OUT,IN), a_w [unused]
    const float* x = (const float*)d_in[0];
    const float* W = (const float*)d_in[2];
    float* out = (float*)d_out;

    const int M = 4 * 2048;   // B * N
    const int N = 256;        // OUT_DIM
    const int K = 256;        // IN_DIM

    dim3 grid(N / BN, M / BM);   // (4, 64) = 256 blocks
    dim3 block(256);
    gat_gemm_nt<<<grid, block>>>(x, W, out, M, N, K);
}

// round 5
// speedup vs baseline: 3.0575x; 3.0575x over previous
#include <cuda_runtime.h>
#include <cuda_fp16.h>
#include <cstdint>

// out = x @ W^T  (GAT attention cancels: softmax rows sum to 1 and the final
// einsum multiplies h by sum_j alpha = 1; adj and a_w are dead inputs).
//   M = 8192, N = 256, K = 256, A=x row-major, B=W row-major (both K-minor).
//
// tcgen05 is unavailable (harness emits .target sm_103 PTX), so use the
// base-ISA tensor path: ldmatrix + mma.sync.m16n8k16 f16 with fp32 accum.
// Single-pass fp16: input-rounding error ~4e-4 l2, under the 1e-3 threshold.

#define THREADS 256
#define BM 128
#define BN 64
#define KC 64           // k-chunk: 64 fp16 = 128B rows (SW128 atom)
#define KGLOB 256
#define NCHUNK 4

__device__ __forceinline__ uint32_t smem_u32(const void* p) {
    uint32_t a;
    asm("{ .reg .u64 t; cvta.to.shared.u64 t, %1; cvt.u32.u64 %0, t; }" : "=r"(a) : "l"(p));
    return a;
}
__device__ __forceinline__ uint32_t swz(uint32_t off) { return off ^ ((off >> 3) & 0x70); }

__device__ __forceinline__ void ldsm4(uint32_t& r0, uint32_t& r1, uint32_t& r2, uint32_t& r3,
                                      uint32_t addr) {
    asm volatile("ldmatrix.sync.aligned.m8n8.x4.shared.b16 {%0,%1,%2,%3}, [%4];"
                 : "=r"(r0), "=r"(r1), "=r"(r2), "=r"(r3) : "r"(addr));
}

__device__ __forceinline__ void mma16816(float* c, const uint32_t* a, const uint32_t* b) {
    asm volatile("mma.sync.aligned.m16n8k16.row.col.f32.f16.f16.f32 "
                 "{%0,%1,%2,%3}, {%4,%5,%6,%7}, {%8,%9}, {%0,%1,%2,%3};"
                 : "+f"(c[0]), "+f"(c[1]), "+f"(c[2]), "+f"(c[3])
                 : "r"(a[0]), "r"(a[1]), "r"(a[2]), "r"(a[3]), "r"(b[0]), "r"(b[1]));
}

__device__ __forceinline__ uint32_t pack2(float x, float y) {
    __half2 h = __floats2half2_rn(x, y);
    return *reinterpret_cast<uint32_t*>(&h);
}

__global__ void __launch_bounds__(THREADS, 2)
gat_hmma_gemm(const float* __restrict__ A, const float* __restrict__ B, float* __restrict__ C)
{
    __shared__ alignas(1024) uint8_t sA[BM * KC * 2];   // 16384 B
    __shared__ alignas(1024) uint8_t sB[BN * KC * 2];   //  8192 B

    const int tid = threadIdx.x;
    const int wid = tid >> 5;
    const int lid = tid & 31;
    const int bm = blockIdx.y, bn = blockIdx.x;
    const int wm = wid & 3;        // 4 warp rows of 32
    const int wn = wid >> 2;       // 2 warp cols of 32

    const uint32_t sAb = smem_u32(sA);
    const uint32_t sBb = smem_u32(sB);

    const float* Ag = A + (size_t)(bm * BM) * KGLOB;
    const float* Bg = B + (size_t)(bn * BN) * KGLOB;

    float acc[2][4][4];
#pragma unroll
    for (int i = 0; i < 2; i++)
#pragma unroll
        for (int j = 0; j < 4; j++)
#pragma unroll
            for (int k = 0; k < 4; k++) acc[i][j][k] = 0.f;

    // ldmatrix lane address components (constant across chunks)
    const uint32_t a_row = (lid & 15);             // + mt*16 + wm*32
    const uint32_t a_cb  = (lid >> 4) * 16;        // + ks*32
    const uint32_t b_row = (lid & 7) + ((lid >> 4) << 3);   // + ntp*16 + wn*32
    const uint32_t b_cb  = ((lid >> 3) & 1) * 16;

    for (int c = 0; c < NCHUNK; c++) {
        // ---- load + convert A tile: 2048 float4, 8/thread ----
#pragma unroll
        for (int i = 0; i < 8; i++) {
            int id = i * THREADS + tid;
            int r  = id >> 4;
            int c4 = id & 15;
            float4 v = *(const float4*)(Ag + (size_t)r * KGLOB + c * KC + c4 * 4);
            uint2 p;
            p.x = pack2(v.x, v.y);
            p.y = pack2(v.z, v.w);
            *(uint2*)(sA + swz((uint32_t)(r * 128 + c4 * 8))) = p;
        }
        // ---- load + convert B tile: 1024 float4, 4/thread ----
#pragma unroll
        for (int i = 0; i < 4; i++) {
            int id = i * THREADS + tid;
            int r  = id >> 4;
            int c4 = id & 15;
            float4 v = *(const float4*)(Bg + (size_t)r * KGLOB + c * KC + c4 * 4);
            uint2 p;
            p.x = pack2(v.x, v.y);
            p.y = pack2(v.z, v.w);
            *(uint2*)(sB + swz((uint32_t)(r * 128 + c4 * 8))) = p;
        }
        __syncthreads();

        // ---- MMA over KC=64: 4 k-steps of 16 ----
#pragma unroll
        for (int ks = 0; ks < 4; ks++) {
            const uint32_t kb = ks * 32;
            uint32_t a[2][4];
#pragma unroll
            for (int mt = 0; mt < 2; mt++) {
                uint32_t row = wm * 32 + mt * 16 + a_row;
                ldsm4(a[mt][0], a[mt][1], a[mt][2], a[mt][3],
                      sAb + swz(row * 128 + kb + a_cb));
            }
            uint32_t b[4][2];
#pragma unroll
            for (int ntp = 0; ntp < 2; ntp++) {
                uint32_t row = wn * 32 + ntp * 16 + b_row;
                ldsm4(b[2 * ntp][0], b[2 * ntp][1], b[2 * ntp + 1][0], b[2 * ntp + 1][1],
                      sBb + swz(row * 128 + kb + b_cb));
            }
#pragma unroll
            for (int mt = 0; mt < 2; mt++)
#pragma unroll
                for (int nt = 0; nt < 4; nt++)
                    mma16816(acc[mt][nt], a[mt], b[nt]);
        }
        __syncthreads();
    }

    // ---- epilogue: direct fp32 stores (float2 per fragment row) ----
    const int g = lid >> 2, tig = lid & 3;
#pragma unroll
    for (int mt = 0; mt < 2; mt++) {
#pragma unroll
        for (int nt = 0; nt < 4; nt++) {
            int row = bm * BM + wm * 32 + mt * 16 + g;
            int col = bn * BN + wn * 32 + nt * 8 + 2 * tig;
            float2 v0 = make_float2(acc[mt][nt][0], acc[mt][nt][1]);
            float2 v1 = make_float2(acc[mt][nt][2], acc[mt][nt][3]);
            *(float2*)(C + (size_t)row * 256 + col) = v0;
            *(float2*)(C + (size_t)(row + 8) * 256 + col) = v1;
        }
    }
}

extern "C" void kernel_launch(void* const* d_in, const int* in_sizes, int n_in,
                              void* d_out, int out_size)
{
    const float* x = (const float*)d_in[0];
    const float* W = (const float*)d_in[2];
    float* out = (float*)d_out;

    dim3 grid(256 / BN, 8192 / BM);   // (4, 64) = 256 CTAs
    gat_hmma_gemm<<<grid, THREADS>>>(x, W, out);
}